// round 1
// baseline (speedup 1.0000x reference)
#include <cuda_runtime.h>
#include <cuda_bf16.h>

// Output layout (flattened f32 concat of the reference tuple):
//   [0, 3V)                      verts_3d   (V x 3)
//   [3V, 3V + Fe)                faces cast to f32 (Fe = in_sizes[3] elements)
//   [3V + Fe, 3V + Fe + V*D)     verts_features copy

__global__ void verts3d_kernel(const float* __restrict__ verts_logit,
                               const float* __restrict__ boundary,
                               float* __restrict__ out, int V) {
    int i = blockIdx.x * blockDim.x + threadIdx.x;
    if (i >= V) return;
    float x, y;
    if (i < 4) {
        x = boundary[2 * i];
        y = boundary[2 * i + 1];
    } else {
        float lx = verts_logit[2 * i];
        float ly = verts_logit[2 * i + 1];
        // sigmoid(l)*2 - 1
        x = 2.0f / (1.0f + __expf(-lx)) - 1.0f;
        y = 2.0f / (1.0f + __expf(-ly)) - 1.0f;
    }
    out[3 * i + 0] = x;
    out[3 * i + 1] = y;
    out[3 * i + 2] = 1.0f;
}

__global__ void faces_cast_kernel(const int* __restrict__ faces,
                                  float* __restrict__ out, int n) {
    int stride = gridDim.x * blockDim.x;
    for (int i = blockIdx.x * blockDim.x + threadIdx.x; i < n; i += stride) {
        out[i] = (float)faces[i];
    }
}

extern "C" void kernel_launch(void* const* d_in, const int* in_sizes, int n_in,
                              void* d_out, int out_size) {
    const float* verts_logit    = (const float*)d_in[0];   // V*2
    const float* verts_features = (const float*)d_in[1];   // V*D
    const float* boundary       = (const float*)d_in[2];   // 4*2
    const int*   faces          = (const int*)d_in[3];     // Fe = F*3 (int32)

    int V2 = in_sizes[0];
    int V  = V2 / 2;
    int feat_elems  = in_sizes[1];
    int faces_elems = in_sizes[3];

    float* out = (float*)d_out;
    float* out_verts3d  = out;                         // 3V
    float* out_faces    = out + (size_t)3 * V;         // faces_elems
    float* out_features = out_faces + faces_elems;     // feat_elems

    // Bulk copy first: 256 MB D2D, this dominates and saturates HBM.
    cudaMemcpyAsync(out_features, verts_features,
                    (size_t)feat_elems * sizeof(float),
                    cudaMemcpyDeviceToDevice);

    {
        int threads = 256;
        int blocks = (V + threads - 1) / threads;
        verts3d_kernel<<<blocks, threads>>>(verts_logit, boundary, out_verts3d, V);
    }
    {
        int threads = 256;
        int blocks = (faces_elems + threads * 4 - 1) / (threads * 4);
        if (blocks < 1) blocks = 1;
        if (blocks > 8192) blocks = 8192;
        faces_cast_kernel<<<blocks, threads>>>(faces, out_faces, faces_elems);
    }
}

// round 2
// speedup vs baseline: 2.0386x; 2.0386x over previous
#include <cuda_runtime.h>
#include <cuda_bf16.h>

// Output layout (flattened f32 concat of the reference tuple):
//   [0, 3V)                      verts_3d   (V x 3)
//   [3V, 3V + Fe)                faces cast to f32 (Fe = in_sizes[3])
//   [3V + Fe, 3V + Fe + V*D)     verts_features copy
//
// One fused kernel over a flat work-item space:
//   items [0, Wfeat)           : features copy, 4 floats/item (float4)
//   items [Wfeat, +Wfaces)     : faces int->float cast, 4 elems/item
//   items [.., +V)             : verts_3d, 1 vertex/item (3 floats out)
// Features region placed FIRST so every block immediately works on the
// bandwidth-dominant copy; tiny regions are the tail of the index space.

__global__ void __launch_bounds__(256) fused_all_kernel(
    const float* __restrict__ verts_logit,
    const float* __restrict__ verts_features,
    const float* __restrict__ boundary,
    const int*   __restrict__ faces,
    float* __restrict__ out,
    int V, int faces_elems, int feat_elems,
    int feat_out_aligned)   // 1 if (3V + faces_elems) % 4 == 0
{
    const long long threeV = 3LL * V;
    float* __restrict__ out_faces    = out + threeV;
    float* __restrict__ out_features = out_faces + faces_elems;

    const int Wfeat  = feat_elems >> 2;          // feat_elems = V*128, %4 == 0
    const int Wfaces = (faces_elems + 3) >> 2;
    const int Wverts = V;
    const long long total = (long long)Wfeat + Wfaces + Wverts;

    const long long stride = (long long)gridDim.x * blockDim.x;
    for (long long idx = (long long)blockIdx.x * blockDim.x + threadIdx.x;
         idx < total; idx += stride) {
        if (idx < Wfeat) {
            // ---- bulk features copy, 16B granularity ----
            const float4 v = __ldg((const float4*)verts_features + idx);
            if (feat_out_aligned) {
                ((float4*)out_features)[idx] = v;
            } else {
                float* d = out_features + (idx << 2);
                d[0] = v.x; d[1] = v.y; d[2] = v.z; d[3] = v.w;
            }
        } else if (idx < (long long)Wfeat + Wfaces) {
            // ---- faces int32 -> float32, 4 elems/item ----
            const int j = (int)(idx - Wfeat);
            const int e = j << 2;
            if (e + 4 <= faces_elems) {
                const int4 f = __ldg((const int4*)faces + j);
                float4 o;
                o.x = (float)f.x; o.y = (float)f.y;
                o.z = (float)f.z; o.w = (float)f.w;
                ((float4*)out_faces)[j] = o;   // out_faces offset 3V %4==0
            } else {
                for (int k = e; k < faces_elems; k++)
                    out_faces[k] = (float)__ldg(faces + k);
            }
        } else {
            // ---- verts_3d: sigmoid(logit)*2-1, first 4 rows = boundary ----
            const int i = (int)(idx - Wfeat - Wfaces);
            float x, y;
            if (i < 4) {
                x = boundary[2 * i];
                y = boundary[2 * i + 1];
            } else {
                const float2 l = __ldg((const float2*)verts_logit + i);
                x = 2.0f / (1.0f + __expf(-l.x)) - 1.0f;
                y = 2.0f / (1.0f + __expf(-l.y)) - 1.0f;
            }
            float* d = out + 3LL * i;
            d[0] = x; d[1] = y; d[2] = 1.0f;
        }
    }
}

extern "C" void kernel_launch(void* const* d_in, const int* in_sizes, int n_in,
                              void* d_out, int out_size) {
    const float* verts_logit    = (const float*)d_in[0];   // V*2
    const float* verts_features = (const float*)d_in[1];   // V*D
    const float* boundary       = (const float*)d_in[2];   // 4*2
    const int*   faces          = (const int*)d_in[3];     // F*3 (int32)

    const int V           = in_sizes[0] / 2;
    const int feat_elems  = in_sizes[1];
    const int faces_elems = in_sizes[3];

    const int feat_out_aligned = (((3LL * V + faces_elems) & 3) == 0) ? 1 : 0;

    const int threads = 256;
    // ~16 blocks per SM worth of grid; grid-stride covers the rest.
    int blocks = 148 * 16;
    const long long total = (long long)(feat_elems >> 2)
                          + ((faces_elems + 3) >> 2) + V;
    const long long need = (total + threads - 1) / threads;
    if (need < blocks) blocks = (int)need;
    if (blocks < 1) blocks = 1;

    fused_all_kernel<<<blocks, threads>>>(
        verts_logit, verts_features, boundary, faces, (float*)d_out,
        V, faces_elems, feat_elems, feat_out_aligned);
}